// round 6
// baseline (speedup 1.0000x reference)
#include <cuda_runtime.h>
#include <cuda_bf16.h>
#include <cstdint>

// Problem constants
#define B_   256
#define T_   256
#define C_   384
#define NH_  8
#define HD_  48
#define KDIM 384

// ---------------------------------------------------------------------------
// Global scratch (static __device__ arrays — no allocation APIs allowed)
// ---------------------------------------------------------------------------
__device__ float g_q[B_ * NH_ * T_ * HD_];    // [B, NH, T, HD]
__device__ float g_k[B_ * NH_ * T_ * HD_];
__device__ float g_v[B_ * NH_ * T_ * HD_];

__device__ __nv_bfloat16 g_xh[B_ * T_ * C_];  // x split hi/lo
__device__ __nv_bfloat16 g_xl[B_ * T_ * C_];
__device__ __nv_bfloat16 g_awh[3 * C_ * C_];  // attn_w split
__device__ __nv_bfloat16 g_awl[3 * C_ * C_];
__device__ __nv_bfloat16 g_pwh[C_ * C_];      // proj_w split
__device__ __nv_bfloat16 g_pwl[C_ * C_];
__device__ __nv_bfloat16 g_ath[B_ * T_ * C_]; // attention output split
__device__ __nv_bfloat16 g_atl[B_ * T_ * C_];

// ---------------------------------------------------------------------------
// PTX helpers
// ---------------------------------------------------------------------------
__device__ __forceinline__ uint32_t smem_to_u32(const void* p) {
    uint32_t a;
    asm("{ .reg .u64 t; cvta.to.shared.u64 t, %1; cvt.u32.u64 %0, t; }"
        : "=r"(a) : "l"(p));
    return a;
}

#define CP_ASYNC16(dst, src) \
    asm volatile("cp.async.cg.shared.global [%0], [%1], 16;" \
                 :: "r"(dst), "l"(src))
#define CP_COMMIT() asm volatile("cp.async.commit_group;" ::: "memory")
#define CP_WAIT1()  asm volatile("cp.async.wait_group 1;" ::: "memory")
#define CP_WAIT0()  asm volatile("cp.async.wait_group 0;" ::: "memory")

__device__ __forceinline__ void ldm_x4(uint32_t r[4], uint32_t addr) {
    asm volatile("ldmatrix.sync.aligned.m8n8.x4.shared.b16 {%0,%1,%2,%3}, [%4];"
                 : "=r"(r[0]), "=r"(r[1]), "=r"(r[2]), "=r"(r[3]) : "r"(addr));
}

__device__ __forceinline__ void mma_bf16(float c[4], const uint32_t a[4], const uint32_t b[2]) {
    asm volatile(
        "mma.sync.aligned.m16n8k16.row.col.f32.bf16.bf16.f32 "
        "{%0,%1,%2,%3}, {%4,%5,%6,%7}, {%8,%9}, {%0,%1,%2,%3};"
        : "+f"(c[0]), "+f"(c[1]), "+f"(c[2]), "+f"(c[3])
        : "r"(a[0]), "r"(a[1]), "r"(a[2]), "r"(a[3]),
          "r"(b[0]), "r"(b[1]));
}

// ---------------------------------------------------------------------------
// Split kernels: fp32 -> bf16 hi + bf16 lo (lo = bf16(a - hi))
// ---------------------------------------------------------------------------
template <int TARGET>
__global__ void split_kernel(const float* __restrict__ src, int n4)
{
    __nv_bfloat16* hi = (TARGET == 0) ? g_xh : (TARGET == 1) ? g_awh : g_pwh;
    __nv_bfloat16* lo = (TARGET == 0) ? g_xl : (TARGET == 1) ? g_awl : g_pwl;
    int i = blockIdx.x * blockDim.x + threadIdx.x;
    const int stride = gridDim.x * blockDim.x;
    for (; i < n4; i += stride) {
        const float4 v = ((const float4*)src)[i];
        __nv_bfloat16 h0 = __float2bfloat16(v.x);
        __nv_bfloat16 h1 = __float2bfloat16(v.y);
        __nv_bfloat16 h2 = __float2bfloat16(v.z);
        __nv_bfloat16 h3 = __float2bfloat16(v.w);
        __nv_bfloat16 l0 = __float2bfloat16(v.x - __bfloat162float(h0));
        __nv_bfloat16 l1 = __float2bfloat16(v.y - __bfloat162float(h1));
        __nv_bfloat16 l2 = __float2bfloat16(v.z - __bfloat162float(h2));
        __nv_bfloat16 l3 = __float2bfloat16(v.w - __bfloat162float(h3));
        ((__nv_bfloat162*)hi)[2 * i + 0] = __nv_bfloat162{h0, h1};
        ((__nv_bfloat162*)hi)[2 * i + 1] = __nv_bfloat162{h2, h3};
        ((__nv_bfloat162*)lo)[2 * i + 0] = __nv_bfloat162{l0, l1};
        ((__nv_bfloat162*)lo)[2 * i + 1] = __nv_bfloat162{l2, l3};
    }
}

// ---------------------------------------------------------------------------
// bf16 3-term compensated GEMM, N-loop INSIDE the kernel for L2 reuse of A.
//   C[n,o] = sum_k A[n,k]*W[o,k] + bias[o]
// grid = 512 row-blocks (BM=128). Each block loops over NT column tiles
// (BN=128), re-reading its A slice from L2 and streaming W (L2-resident).
// 512 threads = 16 warps (4x4), warp tile 32x32. BK=32, 2-stage cp.async.
// MODE 0: QKV, NT=9, scatter epilogue.  MODE 1: proj, NT=3, linear epilogue.
// ---------------------------------------------------------------------------
#define BM 128
#define BN 128
#define BK 32
#define NS (KDIM / BK)            // 12
#define RSB 80                    // smem row stride in bytes (40 bf16)
#define AH_OFF 0
#define AL_OFF (BM * RSB)                 // 10240
#define BH_OFF (2 * BM * RSB)             // 20480
#define BL_OFF (3 * BM * RSB)             // 30720
#define STAGE_B (4 * BM * RSB)            // 40960
#define GEMM_SMEM (2 * STAGE_B)           // 81920

template <int MODE>
__global__ __launch_bounds__(512) void tc_gemm_kernel(
    const float* __restrict__ bias,
    float* __restrict__ out)
{
    extern __shared__ char smem[];
    const uint32_t sbase = smem_to_u32(smem);

    const int NT = (MODE == 0) ? 9 : 3;

    const int tid  = threadIdx.x;
    const int wid  = tid >> 5;
    const int lane = tid & 31;
    const int gid  = lane >> 2;
    const int tig  = lane & 3;

    const int warpM = wid & 3;    // 4 warps in M -> 128 rows
    const int warpN = wid >> 2;   // 4 warps in N -> 128 cols

    const int n0 = blockIdx.x * BM;

    const __nv_bfloat16* Ah = (MODE == 0) ? g_xh : g_ath;
    const __nv_bfloat16* Al = (MODE == 0) ? g_xl : g_atl;
    const __nv_bfloat16* Wh = (MODE == 0) ? g_awh : g_pwh;
    const __nv_bfloat16* Wl = (MODE == 0) ? g_awl : g_pwl;

    // cp.async mapping: 512 16B-chunks per tile (128 rows x 4), 1 per thread.
    const int ld_row = tid >> 2;
    const int ld_ch  = tid & 3;

    const __nv_bfloat16* gAh = Ah + (size_t)(n0 + ld_row) * KDIM + ld_ch * 8;
    const __nv_bfloat16* gAl = Al + (size_t)(n0 + ld_row) * KDIM + ld_ch * 8;

    const uint32_t sOff = (uint32_t)(ld_row * RSB + ld_ch * 16);

    // ldmatrix per-thread byte offsets within a tile
    uint32_t a_off[2];
#pragma unroll
    for (int mi = 0; mi < 2; ++mi)
        a_off[mi] = (uint32_t)((warpM * 32 + mi * 16 + (lane & 15)) * RSB
                               + ((lane >> 4) * 8) * 2);
    uint32_t b_off[2];
#pragma unroll
    for (int tp = 0; tp < 2; ++tp)
        b_off[tp] = (uint32_t)((warpN * 32 + tp * 16 + ((lane >> 4) & 1) * 8 + (lane & 7)) * RSB
                               + (((lane >> 3) & 1) * 8) * 2);

    for (int nt = 0; nt < NT; ++nt) {
        const int o0 = nt * BN;
        const __nv_bfloat16* gWh = Wh + (size_t)(o0 + ld_row) * KDIM + ld_ch * 8;
        const __nv_bfloat16* gWl = Wl + (size_t)(o0 + ld_row) * KDIM + ld_ch * 8;

        float acc[2][4][4];
#pragma unroll
        for (int mi = 0; mi < 2; ++mi)
#pragma unroll
            for (int ni = 0; ni < 4; ++ni)
#pragma unroll
                for (int c = 0; c < 4; ++c) acc[mi][ni][c] = 0.f;

        // prologue: stage 0
        {
            const uint32_t st = sbase;
            CP_ASYNC16(st + AH_OFF + sOff, gAh);
            CP_ASYNC16(st + AL_OFF + sOff, gAl);
            CP_ASYNC16(st + BH_OFF + sOff, gWh);
            CP_ASYNC16(st + BL_OFF + sOff, gWl);
            CP_COMMIT();
        }

        for (int s = 0; s < NS; ++s) {
            if (s + 1 < NS) {
                const uint32_t st = sbase + ((s + 1) & 1) * STAGE_B;
                const int k0 = (s + 1) * BK;
                CP_ASYNC16(st + AH_OFF + sOff, gAh + k0);
                CP_ASYNC16(st + AL_OFF + sOff, gAl + k0);
                CP_ASYNC16(st + BH_OFF + sOff, gWh + k0);
                CP_ASYNC16(st + BL_OFF + sOff, gWl + k0);
                CP_COMMIT();
                CP_WAIT1();
            } else {
                CP_WAIT0();
            }
            __syncthreads();

            const uint32_t st = sbase + (s & 1) * STAGE_B;
#pragma unroll
            for (int kk = 0; kk < 2; ++kk) {             // two k16 steps
                const uint32_t kb = (uint32_t)(kk * 32); // 16 bf16 = 32 bytes
                uint32_t Af[2][4], Alf[2][4];
#pragma unroll
                for (int mi = 0; mi < 2; ++mi) {
                    ldm_x4(Af[mi],  st + AH_OFF + a_off[mi] + kb);
                    ldm_x4(Alf[mi], st + AL_OFF + a_off[mi] + kb);
                }
                uint32_t Bf[2][4], Blf[2][4];
#pragma unroll
                for (int tp = 0; tp < 2; ++tp) {
                    ldm_x4(Bf[tp],  st + BH_OFF + b_off[tp] + kb);
                    ldm_x4(Blf[tp], st + BL_OFF + b_off[tp] + kb);
                }
#pragma unroll
                for (int mi = 0; mi < 2; ++mi)
#pragma unroll
                    for (int ni = 0; ni < 4; ++ni) {
                        const uint32_t* bh = &Bf[ni >> 1][(ni & 1) * 2];
                        const uint32_t* bl = &Blf[ni >> 1][(ni & 1) * 2];
                        mma_bf16(acc[mi][ni], Af[mi],  bh);
                        mma_bf16(acc[mi][ni], Alf[mi], bh);
                        mma_bf16(acc[mi][ni], Af[mi],  bl);
                    }
            }
            __syncthreads();
        }

        // Epilogue for this column tile.
#pragma unroll
        for (int mi = 0; mi < 2; ++mi) {
#pragma unroll
            for (int ci = 0; ci < 2; ++ci) {
                const int row = n0 + warpM * 32 + mi * 16 + gid + ci * 8;
                const int bb = row / T_;
                const int t  = row - bb * T_;
#pragma unroll
                for (int ni = 0; ni < 4; ++ni) {
#pragma unroll
                    for (int cj = 0; cj < 2; ++cj) {
                        const int col = o0 + warpN * 32 + ni * 8 + tig * 2 + cj;
                        const float v = acc[mi][ni][ci * 2 + cj] + bias[col];
                        if (MODE == 0) {
                            const int part = col / C_;          // 0=q, 1=k, 2=v
                            const int c0 = col - part * C_;
                            const int h = c0 / HD_;
                            const int dd = c0 - h * HD_;
                            float* dst = (part == 0) ? g_q : ((part == 1) ? g_k : g_v);
                            dst[(((size_t)bb * NH_ + h) * T_ + t) * HD_ + dd] = v;
                        } else {
                            out[(size_t)row * C_ + col] = v;
                        }
                    }
                }
            }
        }
    }
}

// ---------------------------------------------------------------------------
// Causal flash attention: 1 thread = 1 query row. Online softmax over 16-key
// shared-memory chunks. Emits bf16 hi/lo directly for the proj GEMM.
// grid = (B*NH, T/128), block = 128.
// ---------------------------------------------------------------------------
__global__ __launch_bounds__(128) void attn_kernel()
{
    const int bh = blockIdx.x;
    const int q0 = blockIdx.y * 128;
    const int tid = threadIdx.x;
    const int qi = q0 + tid;

    __shared__ float Ks[16][HD_];
    __shared__ float Vs[16][HD_];

    const float* qp = g_q + ((size_t)bh * T_ + qi) * HD_;
    float qreg[HD_];
#pragma unroll
    for (int d = 0; d < HD_; ++d) qreg[d] = qp[d];

    float acc[HD_];
#pragma unroll
    for (int d = 0; d < HD_; ++d) acc[d] = 0.f;

    float m = -1e30f;
    float l = 0.f;
    const float scale = 0.14433756729740643f;  // 1/sqrt(48)

    const int kend = q0 + 128;

    for (int kc = 0; kc < kend; kc += 16) {
        const float4* kg = (const float4*)(g_k + ((size_t)bh * T_ + kc) * HD_);
        const float4* vg = (const float4*)(g_v + ((size_t)bh * T_ + kc) * HD_);
        float4* ks4 = (float4*)&Ks[0][0];
        float4* vs4 = (float4*)&Vs[0][0];
        __syncthreads();
        for (int i = tid; i < 192; i += 128) {
            ks4[i] = kg[i];
            vs4[i] = vg[i];
        }
        __syncthreads();

        if (kc <= qi) {
            float s[16];
            float mc = -1e30f;
#pragma unroll
            for (int j = 0; j < 16; ++j) {
                float dot = 0.f;
#pragma unroll
                for (int d = 0; d < HD_; ++d)
                    dot = fmaf(qreg[d], Ks[j][d], dot);
                s[j] = (kc + j <= qi) ? dot * scale : -1e30f;
                mc = fmaxf(mc, s[j]);
            }
            const float newm = fmaxf(m, mc);
            const float f = __expf(m - newm);
            l *= f;
#pragma unroll
            for (int d = 0; d < HD_; ++d) acc[d] *= f;
#pragma unroll
            for (int j = 0; j < 16; ++j) {
                const float p = __expf(s[j] - newm);
                l += p;
#pragma unroll
                for (int d = 0; d < HD_; ++d)
                    acc[d] = fmaf(p, Vs[j][d], acc[d]);
            }
            m = newm;
        }
    }

    const float inv = 1.f / l;
    const int bb = bh / NH_;
    const int h  = bh - bb * NH_;
    const size_t base = ((size_t)bb * T_ + qi) * C_ + h * HD_;
#pragma unroll
    for (int d = 0; d < HD_; ++d) {
        const float o = acc[d] * inv;
        const __nv_bfloat16 hi = __float2bfloat16(o);
        g_ath[base + d] = hi;
        g_atl[base + d] = __float2bfloat16(o - __bfloat162float(hi));
    }
}

// ---------------------------------------------------------------------------
extern "C" void kernel_launch(void* const* d_in, const int* in_sizes, int n_in,
                              void* d_out, int out_size)
{
    const float* x      = (const float*)d_in[0];  // [B,T,C]
    const float* attn_w = (const float*)d_in[1];  // [3C, C]
    const float* attn_b = (const float*)d_in[2];  // [3C]
    const float* proj_w = (const float*)d_in[3];  // [C, C]
    const float* proj_b = (const float*)d_in[4];  // [C]
    float* out = (float*)d_out;                   // [B,T,C]

    cudaFuncSetAttribute(tc_gemm_kernel<0>,
                         cudaFuncAttributeMaxDynamicSharedMemorySize, GEMM_SMEM);
    cudaFuncSetAttribute(tc_gemm_kernel<1>,
                         cudaFuncAttributeMaxDynamicSharedMemorySize, GEMM_SMEM);

    // Stage 0: fp32 -> bf16 hi/lo splits
    split_kernel<0><<<2048, 256>>>(x,      B_ * T_ * C_ / 4);
    split_kernel<1><<<432,  256>>>(attn_w, 3 * C_ * C_ / 4);
    split_kernel<2><<<144,  256>>>(proj_w, C_ * C_ / 4);

    // Stage 1: QKV projection + head-major scatter (N-loop inside)
    tc_gemm_kernel<0><<<B_ * T_ / BM, 512, GEMM_SMEM>>>(attn_b, nullptr);

    // Stage 2: causal attention (emits bf16 hi/lo)
    {
        dim3 grid(B_ * NH_, T_ / 128);            // (2048, 2)
        attn_kernel<<<grid, 128>>>();
    }
    // Stage 3: output projection (N-loop inside)
    tc_gemm_kernel<1><<<B_ * T_ / BM, 512, GEMM_SMEM>>>(proj_b, out);
}

// round 7
// speedup vs baseline: 1.7903x; 1.7903x over previous
#include <cuda_runtime.h>
#include <cuda_bf16.h>
#include <cstdint>

// Problem constants
#define B_   256
#define T_   256
#define C_   384
#define NH_  8
#define HD_  48
#define KDIM 384

#define QSCALE 0.20823512f   // (1/sqrt(48)) * log2(e)

// ---------------------------------------------------------------------------
// Global scratch (static __device__ arrays — no allocation APIs allowed)
// ---------------------------------------------------------------------------
__device__ __nv_bfloat16 g_qh[B_ * NH_ * T_ * HD_];  // [B,NH,T,HD], pre-scaled
__device__ __nv_bfloat16 g_ql[B_ * NH_ * T_ * HD_];
__device__ __nv_bfloat16 g_kh[B_ * NH_ * T_ * HD_];  // [B,NH,T,HD]
__device__ __nv_bfloat16 g_kl[B_ * NH_ * T_ * HD_];
__device__ __nv_bfloat16 g_vh[B_ * NH_ * HD_ * T_];  // [B,NH,HD,T] (transposed)
__device__ __nv_bfloat16 g_vl[B_ * NH_ * HD_ * T_];

__device__ __nv_bfloat16 g_xh[B_ * T_ * C_];  // x split hi/lo
__device__ __nv_bfloat16 g_xl[B_ * T_ * C_];
__device__ __nv_bfloat16 g_awh[3 * C_ * C_];  // attn_w split
__device__ __nv_bfloat16 g_awl[3 * C_ * C_];
__device__ __nv_bfloat16 g_pwh[C_ * C_];      // proj_w split
__device__ __nv_bfloat16 g_pwl[C_ * C_];
__device__ __nv_bfloat16 g_ath[B_ * T_ * C_]; // attention output split
__device__ __nv_bfloat16 g_atl[B_ * T_ * C_];

// ---------------------------------------------------------------------------
// PTX helpers
// ---------------------------------------------------------------------------
__device__ __forceinline__ uint32_t smem_to_u32(const void* p) {
    uint32_t a;
    asm("{ .reg .u64 t; cvta.to.shared.u64 t, %1; cvt.u32.u64 %0, t; }"
        : "=r"(a) : "l"(p));
    return a;
}

#define CP_ASYNC16(dst, src) \
    asm volatile("cp.async.cg.shared.global [%0], [%1], 16;" \
                 :: "r"(dst), "l"(src))
#define CP_COMMIT() asm volatile("cp.async.commit_group;" ::: "memory")
#define CP_WAIT1()  asm volatile("cp.async.wait_group 1;" ::: "memory")
#define CP_WAIT0()  asm volatile("cp.async.wait_group 0;" ::: "memory")

__device__ __forceinline__ void ldm_x4(uint32_t r[4], uint32_t addr) {
    asm volatile("ldmatrix.sync.aligned.m8n8.x4.shared.b16 {%0,%1,%2,%3}, [%4];"
                 : "=r"(r[0]), "=r"(r[1]), "=r"(r[2]), "=r"(r[3]) : "r"(addr));
}

__device__ __forceinline__ void mma_bf16(float c[4], const uint32_t a[4], const uint32_t b[2]) {
    asm volatile(
        "mma.sync.aligned.m16n8k16.row.col.f32.bf16.bf16.f32 "
        "{%0,%1,%2,%3}, {%4,%5,%6,%7}, {%8,%9}, {%0,%1,%2,%3};"
        : "+f"(c[0]), "+f"(c[1]), "+f"(c[2]), "+f"(c[3])
        : "r"(a[0]), "r"(a[1]), "r"(a[2]), "r"(a[3]),
          "r"(b[0]), "r"(b[1]));
}

__device__ __forceinline__ float ex2(float x) {
    float y;
    asm("ex2.approx.ftz.f32 %0, %1;" : "=f"(y) : "f"(x));
    return y;
}

// pack two floats (even-k, odd-k) into bf16x2; low half = even-k element
__device__ __forceinline__ uint32_t packbf2(float lo_f, float hi_f) {
    uint32_t r;
    asm("cvt.rn.bf16x2.f32 %0, %1, %2;" : "=r"(r) : "f"(hi_f), "f"(lo_f));
    return r;
}

// ---------------------------------------------------------------------------
// Split kernels: fp32 -> bf16 hi + bf16 lo (lo = bf16(a - hi))
// ---------------------------------------------------------------------------
template <int TARGET>
__global__ void split_kernel(const float* __restrict__ src, int n4)
{
    __nv_bfloat16* hi = (TARGET == 0) ? g_xh : (TARGET == 1) ? g_awh : g_pwh;
    __nv_bfloat16* lo = (TARGET == 0) ? g_xl : (TARGET == 1) ? g_awl : g_pwl;
    int i = blockIdx.x * blockDim.x + threadIdx.x;
    const int stride = gridDim.x * blockDim.x;
    for (; i < n4; i += stride) {
        const float4 v = ((const float4*)src)[i];
        __nv_bfloat16 h0 = __float2bfloat16(v.x);
        __nv_bfloat16 h1 = __float2bfloat16(v.y);
        __nv_bfloat16 h2 = __float2bfloat16(v.z);
        __nv_bfloat16 h3 = __float2bfloat16(v.w);
        __nv_bfloat16 l0 = __float2bfloat16(v.x - __bfloat162float(h0));
        __nv_bfloat16 l1 = __float2bfloat16(v.y - __bfloat162float(h1));
        __nv_bfloat16 l2 = __float2bfloat16(v.z - __bfloat162float(h2));
        __nv_bfloat16 l3 = __float2bfloat16(v.w - __bfloat162float(h3));
        ((__nv_bfloat162*)hi)[2 * i + 0] = __nv_bfloat162{h0, h1};
        ((__nv_bfloat162*)hi)[2 * i + 1] = __nv_bfloat162{h2, h3};
        ((__nv_bfloat162*)lo)[2 * i + 0] = __nv_bfloat162{l0, l1};
        ((__nv_bfloat162*)lo)[2 * i + 1] = __nv_bfloat162{l2, l3};
    }
}

// ---------------------------------------------------------------------------
// bf16 3-term compensated GEMM (R5 structure: BM128/BN64/BK32, 256 thr,
// grid (rows/128, cols/64), 2-stage cp.async).
// MODE 0: QKV; epilogue splits to bf16 hi/lo and scatters to q/k/v arrays
//         (q pre-scaled by QSCALE, v transposed).
// MODE 1: proj; linear epilogue + bias to out.
// ---------------------------------------------------------------------------
#define BM 128
#define BN 64
#define BK 32
#define NS (KDIM / BK)            // 12 stages
#define RSB 80                    // smem row stride in bytes (40 bf16)
#define AH_OFF 0
#define AL_OFF (BM * RSB)
#define BH_OFF (2 * BM * RSB)
#define BL_OFF (2 * BM * RSB + BN * RSB)
#define STAGE_B (2 * BM * RSB + 2 * BN * RSB)   // 30720
#define GEMM_SMEM (2 * STAGE_B)                 // 61440

template <int MODE>
__global__ __launch_bounds__(256) void tc_gemm_kernel(
    const float* __restrict__ bias,
    float* __restrict__ out)
{
    extern __shared__ char smem[];
    const uint32_t sbase = smem_to_u32(smem);

    const int tid  = threadIdx.x;
    const int wid  = tid >> 5;
    const int lane = tid & 31;
    const int gid  = lane >> 2;
    const int tig  = lane & 3;

    const int warpM = wid & 3;
    const int warpN = wid >> 2;

    const int n0 = blockIdx.x * BM;
    const int o0 = blockIdx.y * BN;

    const __nv_bfloat16* Ah = (MODE == 0) ? g_xh : g_ath;
    const __nv_bfloat16* Al = (MODE == 0) ? g_xl : g_atl;
    const __nv_bfloat16* Wh = (MODE == 0) ? g_awh : g_pwh;
    const __nv_bfloat16* Wl = (MODE == 0) ? g_awl : g_pwl;

    const int a_row0 = (tid) >> 2,        a_ch0 = (tid) & 3;
    const int a_row1 = (tid + 256) >> 2,  a_ch1 = (tid + 256) & 3;
    const int b_row  = tid >> 2,          b_ch  = tid & 3;

    const __nv_bfloat16* gAh0 = Ah + (size_t)(n0 + a_row0) * KDIM + a_ch0 * 8;
    const __nv_bfloat16* gAh1 = Ah + (size_t)(n0 + a_row1) * KDIM + a_ch1 * 8;
    const __nv_bfloat16* gAl0 = Al + (size_t)(n0 + a_row0) * KDIM + a_ch0 * 8;
    const __nv_bfloat16* gAl1 = Al + (size_t)(n0 + a_row1) * KDIM + a_ch1 * 8;
    const __nv_bfloat16* gWh  = Wh + (size_t)(o0 + b_row) * KDIM + b_ch * 8;
    const __nv_bfloat16* gWl  = Wl + (size_t)(o0 + b_row) * KDIM + b_ch * 8;

    const uint32_t sA0 = (uint32_t)(a_row0 * RSB + a_ch0 * 16);
    const uint32_t sA1 = (uint32_t)(a_row1 * RSB + a_ch1 * 16);
    const uint32_t sB  = (uint32_t)(b_row * RSB + b_ch * 16);

    uint32_t a_off[2];
#pragma unroll
    for (int mi = 0; mi < 2; ++mi)
        a_off[mi] = (uint32_t)((warpM * 32 + mi * 16 + (lane & 15)) * RSB
                               + ((lane >> 4) * 8) * 2);
    uint32_t b_off[2];
#pragma unroll
    for (int tp = 0; tp < 2; ++tp)
        b_off[tp] = (uint32_t)((warpN * 32 + tp * 16 + ((lane >> 4) & 1) * 8 + (lane & 7)) * RSB
                               + (((lane >> 3) & 1) * 8) * 2);

    float acc[2][4][4];
#pragma unroll
    for (int mi = 0; mi < 2; ++mi)
#pragma unroll
        for (int ni = 0; ni < 4; ++ni)
#pragma unroll
            for (int c = 0; c < 4; ++c) acc[mi][ni][c] = 0.f;

    {
        const uint32_t st = sbase;
        CP_ASYNC16(st + AH_OFF + sA0, gAh0);
        CP_ASYNC16(st + AH_OFF + sA1, gAh1);
        CP_ASYNC16(st + AL_OFF + sA0, gAl0);
        CP_ASYNC16(st + AL_OFF + sA1, gAl1);
        CP_ASYNC16(st + BH_OFF + sB,  gWh);
        CP_ASYNC16(st + BL_OFF + sB,  gWl);
        CP_COMMIT();
    }

    for (int s = 0; s < NS; ++s) {
        if (s + 1 < NS) {
            const uint32_t st = sbase + ((s + 1) & 1) * STAGE_B;
            const int k0 = (s + 1) * BK;
            CP_ASYNC16(st + AH_OFF + sA0, gAh0 + k0);
            CP_ASYNC16(st + AH_OFF + sA1, gAh1 + k0);
            CP_ASYNC16(st + AL_OFF + sA0, gAl0 + k0);
            CP_ASYNC16(st + AL_OFF + sA1, gAl1 + k0);
            CP_ASYNC16(st + BH_OFF + sB,  gWh + k0);
            CP_ASYNC16(st + BL_OFF + sB,  gWl + k0);
            CP_COMMIT();
            CP_WAIT1();
        } else {
            CP_WAIT0();
        }
        __syncthreads();

        const uint32_t st = sbase + (s & 1) * STAGE_B;
#pragma unroll
        for (int kk = 0; kk < 2; ++kk) {
            const uint32_t kb = (uint32_t)(kk * 32);
            uint32_t Af[2][4], Alf[2][4];
#pragma unroll
            for (int mi = 0; mi < 2; ++mi) {
                ldm_x4(Af[mi],  st + AH_OFF + a_off[mi] + kb);
                ldm_x4(Alf[mi], st + AL_OFF + a_off[mi] + kb);
            }
            uint32_t Bf[2][4], Blf[2][4];
#pragma unroll
            for (int tp = 0; tp < 2; ++tp) {
                ldm_x4(Bf[tp],  st + BH_OFF + b_off[tp] + kb);
                ldm_x4(Blf[tp], st + BL_OFF + b_off[tp] + kb);
            }
#pragma unroll
            for (int mi = 0; mi < 2; ++mi)
#pragma unroll
                for (int ni = 0; ni < 4; ++ni) {
                    const uint32_t* bh = &Bf[ni >> 1][(ni & 1) * 2];
                    const uint32_t* bl = &Blf[ni >> 1][(ni & 1) * 2];
                    mma_bf16(acc[mi][ni], Af[mi],  bh);
                    mma_bf16(acc[mi][ni], Alf[mi], bh);
                    mma_bf16(acc[mi][ni], Af[mi],  bl);
                }
        }
        __syncthreads();
    }

#pragma unroll
    for (int mi = 0; mi < 2; ++mi) {
#pragma unroll
        for (int ci = 0; ci < 2; ++ci) {
            const int row = n0 + warpM * 32 + mi * 16 + gid + ci * 8;
            const int bb = row / T_;
            const int t  = row - bb * T_;
#pragma unroll
            for (int ni = 0; ni < 4; ++ni) {
#pragma unroll
                for (int cj = 0; cj < 2; ++cj) {
                    const int col = o0 + warpN * 32 + ni * 8 + tig * 2 + cj;
                    const float v = acc[mi][ni][ci * 2 + cj] + bias[col];
                    if (MODE == 0) {
                        const int part = col / C_;          // 0=q, 1=k, 2=v
                        const int c0 = col - part * C_;
                        const int h = c0 / HD_;
                        const int dd = c0 - h * HD_;
                        const float vv = (part == 0) ? v * QSCALE : v;
                        const __nv_bfloat16 hi = __float2bfloat16(vv);
                        const __nv_bfloat16 lo =
                            __float2bfloat16(vv - __bfloat162float(hi));
                        if (part == 2) {
                            const size_t idx =
                                (((size_t)bb * NH_ + h) * HD_ + dd) * T_ + t;
                            g_vh[idx] = hi; g_vl[idx] = lo;
                        } else {
                            const size_t idx =
                                (((size_t)bb * NH_ + h) * T_ + t) * HD_ + dd;
                            if (part == 0) { g_qh[idx] = hi; g_ql[idx] = lo; }
                            else           { g_kh[idx] = hi; g_kl[idx] = lo; }
                        }
                    } else {
                        out[(size_t)row * C_ + col] = v;
                    }
                }
            }
        }
    }
}

// ---------------------------------------------------------------------------
// Tensorized causal flash attention (FA2 style).
// Block: 128 threads (4 warps), 64 queries; grid = (B*NH, T/64).
// S = QK^T via 3-term compensated bf16 MMA; online softmax in exp2 domain
// (Q pre-scaled); PV via 3-term compensated bf16 MMA with P split in-register.
// Writes attention output as bf16 hi/lo to g_ath/g_atl ([B,T,C]).
// ---------------------------------------------------------------------------
#define QSTR 56      // Q/K smem row stride in bf16 (112 bytes)
#define VSTR 72      // V smem row stride in bf16 (144 bytes)

__global__ __launch_bounds__(128) void attn_kernel()
{
    __shared__ __nv_bfloat16 sQh[64 * QSTR], sQl[64 * QSTR];
    __shared__ __nv_bfloat16 sKh[64 * QSTR], sKl[64 * QSTR];
    __shared__ __nv_bfloat16 sVh[HD_ * VSTR], sVl[HD_ * VSTR];

    const int bh  = blockIdx.x;          // b*NH + h
    const int qt  = blockIdx.y;          // query tile (64 rows)
    const int tid = threadIdx.x;
    const int wid = tid >> 5;
    const int lane = tid & 31;
    const int gid = lane >> 2;
    const int tig = lane & 3;

    const uint32_t uQh = smem_to_u32(sQh), uQl = smem_to_u32(sQl);
    const uint32_t uKh = smem_to_u32(sKh), uKl = smem_to_u32(sKl);
    const uint32_t uVh = smem_to_u32(sVh), uVl = smem_to_u32(sVl);

    // ---- async-load Q tile (64 x 48, hi+lo): 384 chunks of 16B per array
    {
        const size_t qbase = (size_t)bh * T_ * HD_ + (size_t)qt * 64 * HD_;
#pragma unroll
        for (int i = 0; i < 3; ++i) {
            const int c = tid + i * 128;
            const int row = c / 6, ch = c - row * 6;
            const size_t go = qbase + row * HD_ + ch * 8;
            const uint32_t so = (uint32_t)(row * 112 + ch * 16);
            CP_ASYNC16(uQh + so, g_qh + go);
            CP_ASYNC16(uQl + so, g_ql + go);
        }
    }
    CP_COMMIT();

    // ldmatrix offsets
    const uint32_t qa_off = (uint32_t)((wid * 16 + (lane & 15)) * 112
                                       + (lane >> 4) * 16);
    const uint32_t kb_off = (uint32_t)((((lane >> 4) & 1) * 8 + (lane & 7)) * 112
                                       + ((lane >> 3) & 1) * 16);
    const uint32_t vb_off = (uint32_t)((((lane >> 4) & 1) * 8 + (lane & 7)) * VSTR * 2
                                       + ((lane >> 3) & 1) * 16);

    uint32_t qfh[3][4], qfl[3][4];

    float of[6][4];
#pragma unroll
    for (int ni = 0; ni < 6; ++ni)
#pragma unroll
        for (int c = 0; c < 4; ++c) of[ni][c] = 0.f;
    float m0 = -1e30f, m1 = -1e30f, l0 = 0.f, l1 = 0.f;

    const int q0 = qt * 64;
    const int qrow0 = q0 + wid * 16 + gid;
    const int qrow1 = qrow0 + 8;

    for (int kt = 0; kt <= qt; ++kt) {
        // ---- async-load K tile (64x48) and V tile (48x64, transposed layout)
        {
            const size_t kbase = (size_t)bh * T_ * HD_ + (size_t)kt * 64 * HD_;
            const size_t vbase = (size_t)bh * HD_ * T_ + (size_t)kt * 64;
#pragma unroll
            for (int i = 0; i < 3; ++i) {
                const int c = tid + i * 128;
                const int krow = c / 6, kch = c - krow * 6;
                const size_t gk = kbase + krow * HD_ + kch * 8;
                const uint32_t sk = (uint32_t)(krow * 112 + kch * 16);
                CP_ASYNC16(uKh + sk, g_kh + gk);
                CP_ASYNC16(uKl + sk, g_kl + gk);
                const int vrow = c >> 3, vch = c & 7;
                const size_t gv = vbase + (size_t)vrow * T_ + vch * 8;
                const uint32_t sv = (uint32_t)(vrow * (VSTR * 2) + vch * 16);
                CP_ASYNC16(uVh + sv, g_vh + gv);
                CP_ASYNC16(uVl + sv, g_vl + gv);
            }
        }
        CP_COMMIT();
        CP_WAIT0();
        __syncthreads();

        if (kt == 0) {
            // preload Q fragments once (3 k16 steps, hi+lo)
#pragma unroll
            for (int ks = 0; ks < 3; ++ks) {
                ldm_x4(qfh[ks], uQh + qa_off + ks * 32);
                ldm_x4(qfl[ks], uQl + qa_off + ks * 32);
            }
        }

        // ---- S = Q K^T (3-term compensated), 8 n8-tiles of keys
        float sf[8][4];
#pragma unroll
        for (int j = 0; j < 8; ++j)
#pragma unroll
            for (int c = 0; c < 4; ++c) sf[j][c] = 0.f;

#pragma unroll
        for (int ks = 0; ks < 3; ++ks) {
#pragma unroll
            for (int ng = 0; ng < 4; ++ng) {
                uint32_t kfh[4], kfl[4];
                const uint32_t base = ng * 16 * 112 + kb_off + ks * 32;
                ldm_x4(kfh, uKh + base);
                ldm_x4(kfl, uKl + base);
#pragma unroll
                for (int h2 = 0; h2 < 2; ++h2) {
                    const int ni = ng * 2 + h2;
                    mma_bf16(sf[ni], qfh[ks], &kfh[h2 * 2]);
                    mma_bf16(sf[ni], qfl[ks], &kfh[h2 * 2]);
                    mma_bf16(sf[ni], qfh[ks], &kfl[h2 * 2]);
                }
            }
        }

        // ---- causal mask on diagonal tile
        if (kt == qt) {
            const int kb = kt * 64;
#pragma unroll
            for (int j = 0; j < 8; ++j) {
                const int key0 = kb + j * 8 + tig * 2;
                if (key0 > qrow0)     sf[j][0] = -1e30f;
                if (key0 + 1 > qrow0) sf[j][1] = -1e30f;
                if (key0 > qrow1)     sf[j][2] = -1e30f;
                if (key0 + 1 > qrow1) sf[j][3] = -1e30f;
            }
        }

        // ---- online softmax (exp2 domain; scores pre-scaled)
        float mx0 = -1e30f, mx1 = -1e30f;
#pragma unroll
        for (int j = 0; j < 8; ++j) {
            mx0 = fmaxf(mx0, fmaxf(sf[j][0], sf[j][1]));
            mx1 = fmaxf(mx1, fmaxf(sf[j][2], sf[j][3]));
        }
        mx0 = fmaxf(mx0, __shfl_xor_sync(0xffffffffu, mx0, 1));
        mx0 = fmaxf(mx0, __shfl_xor_sync(0xffffffffu, mx0, 2));
        mx1 = fmaxf(mx1, __shfl_xor_sync(0xffffffffu, mx1, 1));
        mx1 = fmaxf(mx1, __shfl_xor_sync(0xffffffffu, mx1, 2));

        const float m0n = fmaxf(m0, mx0);
        const float m1n = fmaxf(m1, mx1);
        const float f0 = ex2(m0 - m0n);
        const float f1 = ex2(m1 - m1n);
        l0 *= f0; l1 *= f1;
#pragma unroll
        for (int ni = 0; ni < 6; ++ni) {
            of[ni][0] *= f0; of[ni][1] *= f0;
            of[ni][2] *= f1; of[ni][3] *= f1;
        }
        float rs0 = 0.f, rs1 = 0.f;
#pragma unroll
        for (int j = 0; j < 8; ++j) {
            sf[j][0] = ex2(sf[j][0] - m0n);
            sf[j][1] = ex2(sf[j][1] - m0n);
            sf[j][2] = ex2(sf[j][2] - m1n);
            sf[j][3] = ex2(sf[j][3] - m1n);
            rs0 += sf[j][0] + sf[j][1];
            rs1 += sf[j][2] + sf[j][3];
        }
        rs0 += __shfl_xor_sync(0xffffffffu, rs0, 1);
        rs0 += __shfl_xor_sync(0xffffffffu, rs0, 2);
        rs1 += __shfl_xor_sync(0xffffffffu, rs1, 1);
        rs1 += __shfl_xor_sync(0xffffffffu, rs1, 2);
        l0 += rs0; l1 += rs1;
        m0 = m0n; m1 = m1n;

        // ---- O += P V (3-term compensated; P split in-register)
#pragma unroll
        for (int kk = 0; kk < 4; ++kk) {
            const int j0 = kk * 2, j1 = j0 + 1;
            uint32_t pa[4], pal[4];
            // a0/a1 from tile j0 (k 0-7), a2/a3 from tile j1 (k 8-15)
            pa[0] = packbf2(sf[j0][0], sf[j0][1]);
            pa[1] = packbf2(sf[j0][2], sf[j0][3]);
            pa[2] = packbf2(sf[j1][0], sf[j1][1]);
            pa[3] = packbf2(sf[j1][2], sf[j1][3]);
#pragma unroll
            for (int r = 0; r < 4; ++r) {
                const int jj = (r >> 1) ? j1 : j0;
                const int cc = (r & 1) * 2;
                const float e0 = __uint_as_float(pa[r] << 16);
                const float e1 = __uint_as_float(pa[r] & 0xFFFF0000u);
                pal[r] = packbf2(sf[jj][cc] - e0, sf[jj][cc + 1] - e1);
            }
#pragma unroll
            for (int ng = 0; ng < 3; ++ng) {
                uint32_t vfh[4], vfl[4];
                const uint32_t base = ng * 16 * (VSTR * 2) + vb_off + kk * 32;
                ldm_x4(vfh, uVh + base);
                ldm_x4(vfl, uVl + base);
#pragma unroll
                for (int h2 = 0; h2 < 2; ++h2) {
                    const int ni = ng * 2 + h2;
                    mma_bf16(of[ni], pa,  &vfh[h2 * 2]);
                    mma_bf16(of[ni], pal, &vfh[h2 * 2]);
                    mma_bf16(of[ni], pa,  &vfl[h2 * 2]);
                }
            }
        }
        __syncthreads();
    }

    // ---- epilogue: normalize and write bf16 hi/lo to g_ath/g_atl
    const float inv0 = 1.f / l0;
    const float inv1 = 1.f / l1;
    const int b = bh >> 3;
    const int h = bh & 7;
    const size_t ob0 = ((size_t)b * T_ + qrow0) * C_ + h * HD_;
    const size_t ob1 = ((size_t)b * T_ + qrow1) * C_ + h * HD_;
#pragma unroll
    for (int ni = 0; ni < 6; ++ni) {
        const int col = ni * 8 + tig * 2;
        {
            const float a = of[ni][0] * inv0, bv = of[ni][1] * inv0;
            const uint32_t hi = packbf2(a, bv);
            const float e0 = __uint_as_float(hi << 16);
            const float e1 = __uint_as_float(hi & 0xFFFF0000u);
            const uint32_t lo = packbf2(a - e0, bv - e1);
            *(uint32_t*)(g_ath + ob0 + col) = hi;
            *(uint32_t*)(g_atl + ob0 + col) = lo;
        }
        {
            const float a = of[ni][2] * inv1, bv = of[ni][3] * inv1;
            const uint32_t hi = packbf2(a, bv);
            const float e0 = __uint_as_float(hi << 16);
            const float e1 = __uint_as_float(hi & 0xFFFF0000u);
            const uint32_t lo = packbf2(a - e0, bv - e1);
            *(uint32_t*)(g_ath + ob1 + col) = hi;
            *(uint32_t*)(g_atl + ob1 + col) = lo;
        }
    }
}

// ---------------------------------------------------------------------------
extern "C" void kernel_launch(void* const* d_in, const int* in_sizes, int n_in,
                              void* d_out, int out_size)
{
    const float* x      = (const float*)d_in[0];  // [B,T,C]
    const float* attn_w = (const float*)d_in[1];  // [3C, C]
    const float* attn_b = (const float*)d_in[2];  // [3C]
    const float* proj_w = (const float*)d_in[3];  // [C, C]
    const float* proj_b = (const float*)d_in[4];  // [C]
    float* out = (float*)d_out;                   // [B,T,C]

    cudaFuncSetAttribute(tc_gemm_kernel<0>,
                         cudaFuncAttributeMaxDynamicSharedMemorySize, GEMM_SMEM);
    cudaFuncSetAttribute(tc_gemm_kernel<1>,
                         cudaFuncAttributeMaxDynamicSharedMemorySize, GEMM_SMEM);

    // Stage 0: fp32 -> bf16 hi/lo splits
    split_kernel<0><<<2048, 256>>>(x,      B_ * T_ * C_ / 4);
    split_kernel<1><<<432,  256>>>(attn_w, 3 * C_ * C_ / 4);
    split_kernel<2><<<144,  256>>>(proj_w, C_ * C_ / 4);

    // Stage 1: QKV projection + bf16 hi/lo scatter (q scaled, v transposed)
    {
        dim3 grid(B_ * T_ / BM, (3 * C_) / BN);   // (512, 18)
        tc_gemm_kernel<0><<<grid, 256, GEMM_SMEM>>>(attn_b, nullptr);
    }
    // Stage 2: tensorized causal attention
    {
        dim3 grid(B_ * NH_, T_ / 64);             // (2048, 4)
        attn_kernel<<<grid, 128>>>();
    }
    // Stage 3: output projection
    {
        dim3 grid(B_ * T_ / BM, C_ / BN);         // (512, 6)
        tc_gemm_kernel<1><<<grid, 256, GEMM_SMEM>>>(proj_b, out);
    }
}